// round 4
// baseline (speedup 1.0000x reference)
#include <cuda_runtime.h>
#include <math.h>

#define NN 100000
#define OC 128

// Scratch (device globals: allowed; no allocation in kernel_launch)
__device__ __align__(16) float g_A [(size_t)NN * OC];
__device__ __align__(16) float g_B [(size_t)NN * OC];
__device__ __align__(16) float g_x2[(size_t)NN * OC];
__device__ __align__(16) float g_x4[(size_t)NN * OC];
__device__ __align__(16) float g_x6[(size_t)NN * OC];

// 1 if edge_index is stored as int64 words, 0 if int32.
__device__ int g_idx64;

// ---------------------------------------------------------------------------
// Detect edge-index width. Indices < 2^31, so if the array is int64 every odd
// 32-bit word is zero. Sample 2048 odd words: all zero => int64 layout.
// ---------------------------------------------------------------------------
__global__ void detect_idx_kernel(const int* __restrict__ ei)
{
    __shared__ int any;
    if (threadIdx.x == 0) any = 0;
    __syncthreads();
    for (int i = threadIdx.x; i < 2048; i += blockDim.x)
        if (ei[2 * i + 1] != 0) any = 1;
    __syncthreads();
    if (threadIdx.x == 0) g_idx64 = (any == 0) ? 1 : 0;
}

// ---------------------------------------------------------------------------
// Node transform: A = x @ (Wtop - Wbot) + ba ;  B = x @ Wbot ; outz = 0
// wa is [2C, 128] row-major. Block: 128 threads (one per output channel),
// NPB nodes per block with x rows staged in smem (broadcast reads).
// ---------------------------------------------------------------------------
template<int C, int NPB>
__global__ __launch_bounds__(128)
void node_kernel(const float* __restrict__ x,
                 const float* __restrict__ wa,
                 const float* __restrict__ ba,
                 float* __restrict__ A,
                 float* __restrict__ B,
                 float* __restrict__ outz,
                 int n_nodes)
{
    __shared__ float xs[NPB * C];
    const int n0  = blockIdx.x * NPB;
    const int tid = threadIdx.x;

    for (int i = tid; i < NPB * C; i += 128) {
        int nn = i / C, c = i % C;
        int n = n0 + nn;
        xs[i] = (n < n_nodes) ? x[(size_t)n * C + c] : 0.f;
    }
    __syncthreads();

    float a[NPB], b[NPB];
#pragma unroll
    for (int t = 0; t < NPB; t++) { a[t] = 0.f; b[t] = 0.f; }

    const int o = tid;
#pragma unroll 4
    for (int c = 0; c < C; c++) {
        float wtop = wa[(size_t)c       * OC + o];
        float wbot = wa[(size_t)(C + c) * OC + o];
        float wd   = wtop - wbot;
#pragma unroll
        for (int t = 0; t < NPB; t++) {
            float xv = xs[t * C + c];
            a[t] += xv * wd;
            b[t] += xv * wbot;
        }
    }
    float bao = ba[o];
#pragma unroll
    for (int t = 0; t < NPB; t++) {
        int n = n0 + t;
        if (n < n_nodes) {
            size_t idx = (size_t)n * OC + o;
            A[idx]    = a[t] + bao;
            B[idx]    = b[t];
            outz[idx] = 0.f;   // zero-init aggregation target
        }
    }
}

// ---------------------------------------------------------------------------
// Edge kernel: per edge  h = relu(A[dst] + B[src]);  m = h @ wb + bb;
// atomicMax (signed-int bits, valid: running value >= +0 bits) into out[dst].
// One warp processes 4 edges; wb (64KB) + bb staged in dynamic smem.
// Lane j holds outputs [4j, 4j+4); h[k] lives in lane k/4 component k%4,
// broadcast via shfl.
// ---------------------------------------------------------------------------
__global__ __launch_bounds__(256)
void edge_kernel(const float4* __restrict__ A4,
                 const float4* __restrict__ B4,
                 const void* __restrict__ ei,     // raw edge_index buffer
                 const float* __restrict__ wb,
                 const float* __restrict__ bb,
                 float* __restrict__ out,
                 long long E)
{
    extern __shared__ float4 sm[];
    float4* wbs = sm;            // [128 * 32] : wbs[k*32 + j] = wb[k][4j..4j+3]
    float4* bbs = sm + 128 * 32; // [32]

    const int tid = threadIdx.x;
    for (int i = tid; i < 128 * 32; i += blockDim.x)
        wbs[i] = ((const float4*)wb)[i];
    if (tid < 32) bbs[tid] = ((const float4*)bb)[tid];
    __syncthreads();

    const int idx64 = g_idx64;
    const int* __restrict__       ei32 = (const int*)ei;
    const long long* __restrict__ ei64 = (const long long*)ei;

    const int lane   = tid & 31;
    const int warp   = blockIdx.x * (blockDim.x >> 5) + (tid >> 5);
    const int nwarps = gridDim.x * (blockDim.x >> 5);
    const unsigned FULL = 0xffffffffu;

    for (long long base = (long long)warp * 4; base < E;
         base += (long long)nwarps * 4) {
        float4 h[4];
        long long dd[4];
        int cnt = (int)min((long long)4, E - base);

#pragma unroll
        for (int t = 0; t < 4; t++) {
            if (t < cnt) {
                long long e = base + t;
                long long s, d;
                if (idx64) { s = ei64[e]; d = ei64[E + e]; }
                else       { s = ei32[e]; d = ei32[E + e]; }
                dd[t] = d;
                float4 av = A4[d * 32 + lane];
                float4 bv = B4[s * 32 + lane];
                float4 hv;
                hv.x = fmaxf(av.x + bv.x, 0.f);
                hv.y = fmaxf(av.y + bv.y, 0.f);
                hv.z = fmaxf(av.z + bv.z, 0.f);
                hv.w = fmaxf(av.w + bv.w, 0.f);
                h[t] = hv;
            } else {
                h[t] = make_float4(0.f, 0.f, 0.f, 0.f);
                dd[t] = -1;
            }
        }

        float4 m[4];
        float4 bv0 = bbs[lane];
#pragma unroll
        for (int t = 0; t < 4; t++) m[t] = bv0;

#pragma unroll 4
        for (int ks = 0; ks < 32; ks++) {
            float4 w0 = wbs[(ks * 4 + 0) * 32 + lane];
            float4 w1 = wbs[(ks * 4 + 1) * 32 + lane];
            float4 w2 = wbs[(ks * 4 + 2) * 32 + lane];
            float4 w3 = wbs[(ks * 4 + 3) * 32 + lane];
#pragma unroll
            for (int t = 0; t < 4; t++) {
                float hx = __shfl_sync(FULL, h[t].x, ks);
                float hy = __shfl_sync(FULL, h[t].y, ks);
                float hz = __shfl_sync(FULL, h[t].z, ks);
                float hw = __shfl_sync(FULL, h[t].w, ks);
                m[t].x += hx * w0.x + hy * w1.x + hz * w2.x + hw * w3.x;
                m[t].y += hx * w0.y + hy * w1.y + hz * w2.y + hw * w3.y;
                m[t].z += hx * w0.z + hy * w1.z + hz * w2.z + hw * w3.z;
                m[t].w += hx * w0.w + hy * w1.w + hz * w2.w + hw * w3.w;
            }
        }

#pragma unroll
        for (int t = 0; t < 4; t++) {
            if (t < cnt) {
                int* o = (int*)(out + dd[t] * OC + lane * 4);
                atomicMax(o + 0, __float_as_int(m[t].x));
                atomicMax(o + 1, __float_as_int(m[t].y));
                atomicMax(o + 2, __float_as_int(m[t].z));
                atomicMax(o + 3, __float_as_int(m[t].w));
            }
        }
    }
}

// ---------------------------------------------------------------------------
// Final: x7 = concat(x2,x4,x6) [384]; maxpool groups of 24 -> 16; @ fw + fb.
// One warp per node: lane covers indices [12*lane, 12*lane+12) => half of
// group lane/2; pairwise shfl for group max; warp-sum for the dot product.
// ---------------------------------------------------------------------------
__global__ __launch_bounds__(256)
void final_kernel(const float* __restrict__ x2,
                  const float* __restrict__ x4,
                  const float* __restrict__ x6,
                  const float* __restrict__ fw,
                  const float* __restrict__ fb,
                  float* __restrict__ out,
                  int n_nodes)
{
    const unsigned FULL = 0xffffffffu;
    const int lane = threadIdx.x & 31;
    const int warp = blockIdx.x * (blockDim.x >> 5) + (threadIdx.x >> 5);
    const int nw   = gridDim.x * (blockDim.x >> 5);

    for (int n = warp; n < n_nodes; n += nw) {
        float m = -3.4e38f;
        int idx0 = lane * 12;
#pragma unroll
        for (int i = 0; i < 12; i++) {
            int idx = idx0 + i;
            float v;
            if (idx < 128)       v = x2[(size_t)n * OC + idx];
            else if (idx < 256)  v = x4[(size_t)n * OC + idx - 128];
            else                 v = x6[(size_t)n * OC + idx - 256];
            m = fmaxf(m, v);
        }
        float mm = fmaxf(m, __shfl_xor_sync(FULL, m, 1));
        float part = ((lane & 1) == 0) ? mm * fw[lane >> 1] : 0.f;
#pragma unroll
        for (int off = 16; off >= 1; off >>= 1)
            part += __shfl_xor_sync(FULL, part, off);
        if (lane == 0) out[n] = part + fb[0];
    }
}

// ---------------------------------------------------------------------------
extern "C" void kernel_launch(void* const* d_in, const int* in_sizes, int n_in,
                              void* d_out, int out_size)
{
    const float* x   = (const float*)d_in[0];
    const void*  ei  = d_in[1];
    const float* w1a = (const float*)d_in[2];  const float* b1a = (const float*)d_in[3];
    const float* w1b = (const float*)d_in[4];  const float* b1b = (const float*)d_in[5];
    const float* w2a = (const float*)d_in[6];  const float* b2a = (const float*)d_in[7];
    const float* w2b = (const float*)d_in[8];  const float* b2b = (const float*)d_in[9];
    const float* w3a = (const float*)d_in[10]; const float* b3a = (const float*)d_in[11];
    const float* w3b = (const float*)d_in[12]; const float* b3b = (const float*)d_in[13];
    const float* fw  = (const float*)d_in[14]; const float* fb  = (const float*)d_in[15];
    float* out = (float*)d_out;

    const int       N = in_sizes[0] / 24;
    const long long E = in_sizes[1] / 2;

    float *A, *B, *X2, *X4, *X6;
    cudaGetSymbolAddress((void**)&A,  g_A);
    cudaGetSymbolAddress((void**)&B,  g_B);
    cudaGetSymbolAddress((void**)&X2, g_x2);
    cudaGetSymbolAddress((void**)&X4, g_x4);
    cudaGetSymbolAddress((void**)&X6, g_x6);

    const int SMEM_EDGE = (128 * 32 + 32) * (int)sizeof(float4);  // 66048 B
    cudaFuncSetAttribute(edge_kernel,
                         cudaFuncAttributeMaxDynamicSharedMemorySize, SMEM_EDGE);

    const int NPB = 8;
    const int node_grid = (N + NPB - 1) / NPB;
    const int edge_grid = 1184;   // 148 SMs * 8 blocks, grid-stride inside

    // Determine edge-index word width (int32 vs int64) on device.
    detect_idx_kernel<<<1, 256>>>((const int*)ei);

    // Layer 1 (C = 24)
    node_kernel<24, 8><<<node_grid, 128>>>(x, w1a, b1a, A, B, X2, N);
    edge_kernel<<<edge_grid, 256, SMEM_EDGE>>>((const float4*)A, (const float4*)B,
                                               ei, w1b, b1b, X2, E);
    // Layer 2 (C = 128)
    node_kernel<128, 8><<<node_grid, 128>>>(X2, w2a, b2a, A, B, X4, N);
    edge_kernel<<<edge_grid, 256, SMEM_EDGE>>>((const float4*)A, (const float4*)B,
                                               ei, w2b, b2b, X4, E);
    // Layer 3 (C = 128)
    node_kernel<128, 8><<<node_grid, 128>>>(X4, w3a, b3a, A, B, X6, N);
    edge_kernel<<<edge_grid, 256, SMEM_EDGE>>>((const float4*)A, (const float4*)B,
                                               ei, w3b, b3b, X6, E);

    // Pool + final linear
    final_kernel<<<(N + 7) / 8, 256>>>(X2, X4, X6, fw, fb, out, N);
}

// round 6
// speedup vs baseline: 1.9375x; 1.9375x over previous
#include <cuda_runtime.h>
#include <cuda_bf16.h>
#include <math.h>
#include <stdint.h>

#define NN   100000
#define OC   128
#define MAXE 1600000

// ---------------------------------------------------------------------------
// Device scratch
// ---------------------------------------------------------------------------
__device__ __align__(16) float g_A [(size_t)NN * OC];
__device__ __align__(16) float g_B [(size_t)NN * OC];
__device__ __align__(16) float g_x2[(size_t)NN * OC];
__device__ __align__(16) float g_x4[(size_t)NN * OC];
__device__ __align__(16) float g_x6[(size_t)NN * OC];

__device__ int g_deg[NN];
__device__ int g_off[NN + 1];
__device__ int g_cur[NN];
__device__ int g_ssrc[MAXE];
__device__ int g_sdst[MAXE];
// Pre-packed tf32 B operand per layer: [pair p(8)][kstep(16)][lane(32)] uint4
__device__ __align__(16) uint4 g_wbp[3][4096];
__device__ int g_idx64;

// ---------------------------------------------------------------------------
// tf32 helpers
// ---------------------------------------------------------------------------
__device__ __forceinline__ uint32_t f2tf32(float f) {
    uint32_t r;
    asm("cvt.rna.tf32.f32 %0, %1;" : "=r"(r) : "f"(f));
    return r;
}

__device__ __forceinline__ void mma_tf32(float* d, const uint32_t* a,
                                         uint32_t b0, uint32_t b1) {
    asm volatile(
        "mma.sync.aligned.m16n8k8.row.col.f32.tf32.tf32.f32 "
        "{%0,%1,%2,%3}, {%4,%5,%6,%7}, {%8,%9}, {%0,%1,%2,%3};"
        : "+f"(d[0]), "+f"(d[1]), "+f"(d[2]), "+f"(d[3])
        : "r"(a[0]), "r"(a[1]), "r"(a[2]), "r"(a[3]), "r"(b0), "r"(b1));
}

// ---------------------------------------------------------------------------
// Index-width detection (int32 vs int64 edge_index)
// ---------------------------------------------------------------------------
__global__ void detect_idx_kernel(const int* __restrict__ ei)
{
    __shared__ int any;
    if (threadIdx.x == 0) any = 0;
    __syncthreads();
    for (int i = threadIdx.x; i < 2048; i += blockDim.x)
        if (ei[2 * i + 1] != 0) any = 1;
    __syncthreads();
    if (threadIdx.x == 0) g_idx64 = (any == 0) ? 1 : 0;
}

// ---------------------------------------------------------------------------
// Counting sort by dst
// ---------------------------------------------------------------------------
__global__ void hist_kernel(const void* __restrict__ ei, long long E, int* __restrict__ deg)
{
    const int idx64 = g_idx64;
    long long i = (long long)blockIdx.x * blockDim.x + threadIdx.x;
    const long long stride = (long long)gridDim.x * blockDim.x;
    for (; i < E; i += stride) {
        int d = idx64 ? (int)((const long long*)ei)[E + i] : ((const int*)ei)[E + i];
        atomicAdd(&deg[d], 1);
    }
}

__global__ void scan_kernel(const int* __restrict__ deg, int* __restrict__ off, int n)
{
    __shared__ int sc[1024];
    __shared__ int carry;
    const int tid = threadIdx.x;
    if (tid == 0) carry = 0;
    __syncthreads();
    for (int base = 0; base < n; base += 1024) {
        int i = base + tid;
        int v = (i < n) ? deg[i] : 0;
        sc[tid] = v;
        __syncthreads();
        int run = v;
        for (int d = 1; d < 1024; d <<= 1) {
            int add = (tid >= d) ? sc[tid - d] : 0;
            __syncthreads();
            run += add;
            sc[tid] = run;
            __syncthreads();
        }
        int c = carry;
        if (i < n) off[i] = c + run - v;
        __syncthreads();
        if (tid == 0) carry = c + sc[1023];
        __syncthreads();
    }
    if (tid == 0) off[n] = carry;
}

__global__ void scatter_kernel(const void* __restrict__ ei, long long E,
                               const int* __restrict__ off, int* __restrict__ cur,
                               int* __restrict__ ssrc, int* __restrict__ sdst)
{
    const int idx64 = g_idx64;
    long long i = (long long)blockIdx.x * blockDim.x + threadIdx.x;
    const long long stride = (long long)gridDim.x * blockDim.x;
    for (; i < E; i += stride) {
        int s, d;
        if (idx64) { s = (int)((const long long*)ei)[i]; d = (int)((const long long*)ei)[E + i]; }
        else       { s = ((const int*)ei)[i];            d = ((const int*)ei)[E + i]; }
        int p = off[d] + atomicAdd(&cur[d], 1);
        ssrc[p] = s;
        sdst[p] = d;
    }
}

// ---------------------------------------------------------------------------
// Pack wb [K=128 in][N=128 out] into per-lane tf32 B fragments:
// out[((p*16 + kk)*32 + lane)] = { W[k0][n0], W[k0+4][n0], W[k0][n0+8], W[k0+4][n0+8] }
// with k0 = kk*8 + lane%4, n0 = p*16 + lane/4   (m16n8k8 col-major B mapping)
// ---------------------------------------------------------------------------
__global__ void prep_w_kernel(const float* __restrict__ wb, uint4* __restrict__ outp)
{
    int idx = blockIdx.x * blockDim.x + threadIdx.x;
    if (idx >= 4096) return;
    int lane = idx & 31;
    int kk   = (idx >> 5) & 15;
    int p    = idx >> 9;
    int k0 = kk * 8 + (lane & 3);
    int n0 = p * 16 + (lane >> 2);
    uint4 v;
    v.x = f2tf32(wb[k0 * 128 + n0]);
    v.y = f2tf32(wb[(k0 + 4) * 128 + n0]);
    v.z = f2tf32(wb[k0 * 128 + n0 + 8]);
    v.w = f2tf32(wb[(k0 + 4) * 128 + n0 + 8]);
    outp[idx] = v;
}

// ---------------------------------------------------------------------------
// Node transform: A = x @ (Wtop - Wbot) + ba ;  B = x @ Wbot ; outz = 0
// ---------------------------------------------------------------------------
template<int C, int NPB>
__global__ __launch_bounds__(128)
void node_kernel(const float* __restrict__ x,
                 const float* __restrict__ wa,
                 const float* __restrict__ ba,
                 float* __restrict__ A,
                 float* __restrict__ B,
                 float* __restrict__ outz,
                 int n_nodes)
{
    __shared__ float xs[NPB * C];
    const int n0  = blockIdx.x * NPB;
    const int tid = threadIdx.x;

    for (int i = tid; i < NPB * C; i += 128) {
        int nn = i / C, c = i % C;
        int n = n0 + nn;
        xs[i] = (n < n_nodes) ? x[(size_t)n * C + c] : 0.f;
    }
    __syncthreads();

    float a[NPB], b[NPB];
#pragma unroll
    for (int t = 0; t < NPB; t++) { a[t] = 0.f; b[t] = 0.f; }

    const int o = tid;
#pragma unroll 4
    for (int c = 0; c < C; c++) {
        float wtop = wa[(size_t)c       * OC + o];
        float wbot = wa[(size_t)(C + c) * OC + o];
        float wd   = wtop - wbot;
#pragma unroll
        for (int t = 0; t < NPB; t++) {
            float xv = xs[t * C + c];
            a[t] += xv * wd;
            b[t] += xv * wbot;
        }
    }
    float bao = ba[o];
#pragma unroll
    for (int t = 0; t < NPB; t++) {
        int n = n0 + t;
        if (n < n_nodes) {
            size_t idx = (size_t)n * OC + o;
            A[idx]    = a[t] + bao;
            B[idx]    = b[t];
            outz[idx] = 0.f;
        }
    }
}

// ---------------------------------------------------------------------------
// Edge kernel (mma.sync tf32, sorted edges).
// Per 128-edge tile:
//   H[e][k] = tf32(relu(A[dst]+B[src]))  -> smem (padded rows)
//   D[128 e][128 out] = H @ Wb  via m16n8k8 tf32 mma, warp tile 32x64
//   D -> smem msg[e][c], segmented max over contiguous dst runs + bias,
//   plain store interior segments, atomicMax(int-bits) on tile boundaries.
// ---------------------------------------------------------------------------
#define HP 132  // padded row length (floats) for H / msg

#define SM_H     0                         // 128*132*4 = 67584
#define SM_WB    67584                     // 4096 * 16  = 65536
#define SM_SDST  (SM_WB + 65536)           // 133120, int[128]
#define SM_SSRC  (SM_SDST + 512)           // int[128]
#define SM_SEGS  (SM_SSRC + 512)           // int[136]
#define SM_SEGN  (SM_SEGS + 544)           // int[128]
#define SM_BB    (SM_SEGN + 512)           // float[128]
#define SM_WC    (SM_BB + 512)             // int[8]
#define SM_NSEG  (SM_WC + 32)              // int[4]
#define SM_TOTAL (SM_NSEG + 16)

__global__ __launch_bounds__(256, 1)
void edge_mma_kernel(const float4* __restrict__ nodeA,
                     const float4* __restrict__ nodeB,
                     const int* __restrict__ ssrc_g,
                     const int* __restrict__ sdst_g,
                     const uint4* __restrict__ wbp,
                     const float* __restrict__ bb,
                     float* __restrict__ out,
                     int E)
{
    extern __shared__ __align__(16) char smem[];
    const int tid  = threadIdx.x;
    const int wid  = tid >> 5;
    const int lane = tid & 31;
    const unsigned FULL = 0xffffffffu;

    uint32_t* Hs   = (uint32_t*)(smem + SM_H);
    float*    msg  = (float*)(smem + SM_H);      // same region, after MMA
    uint4*    wbs  = (uint4*)(smem + SM_WB);
    int*      sdst = (int*)(smem + SM_SDST);
    int*      ssrc = (int*)(smem + SM_SSRC);
    int*      segs = (int*)(smem + SM_SEGS);
    int*      segn = (int*)(smem + SM_SEGN);
    float*    bbs  = (float*)(smem + SM_BB);
    int*      swc  = (int*)(smem + SM_WC);
    int*      snseg= (int*)(smem + SM_NSEG);

    // persistent: packed weights + bias
    for (int i = tid; i < 4096; i += 256) wbs[i] = wbp[i];
    if (tid < 128) bbs[tid] = bb[tid];
    __syncthreads();

    const int ntiles = (E + 127) >> 7;
    const int wM = wid & 3;      // edge-stripe  [wM*32, +32)
    const int wN = wid >> 2;     // out-half     [wN*64, +64)

    for (int t = blockIdx.x; t < ntiles; t += gridDim.x) {
        const int e0  = t << 7;
        const int cnt = min(128, E - e0);

        if (tid < 128) {
            sdst[tid] = (tid < cnt) ? sdst_g[e0 + tid] : -1;
            ssrc[tid] = (tid < cnt) ? ssrc_g[e0 + tid] : 0;
        }
        __syncthreads();

        // ---- segment heads (warps 0..3) ----
        int head = 0; unsigned bm = 0;
        if (tid < 128) {
            head = (tid < cnt) && (tid == 0 || sdst[tid] != sdst[tid - 1]);
            bm = __ballot_sync(FULL, head);
            if (lane == 0) swc[wid] = __popc(bm);
        }
        __syncthreads();
        if (tid == 0) {
            int s = 0;
            for (int w = 0; w < 4; w++) { swc[4 + w] = s; s += swc[w]; }
            snseg[0] = s;
            segs[s]  = cnt;
        }
        __syncthreads();
        if (head) {
            int sid = swc[4 + wid] + __popc(bm & ((1u << lane) - 1u));
            segs[sid] = tid;
            segn[sid] = sdst[tid];
        }

        // ---- gather: H[e][k] = tf32(relu(A[dst]+B[src])) ----
        {
            const int e    = tid >> 1;
            const int half = tid & 1;
            uint32_t* hr = Hs + e * HP + half * 64;
            if (e < cnt) {
                const size_t dr = (size_t)sdst[e] * 32 + half * 16;
                const size_t sr = (size_t)ssrc[e] * 32 + half * 16;
#pragma unroll
                for (int j = 0; j < 16; j++) {
                    float4 av = nodeA[dr + j];
                    float4 bv = nodeB[sr + j];
                    uint4 hv;
                    hv.x = f2tf32(fmaxf(av.x + bv.x, 0.f));
                    hv.y = f2tf32(fmaxf(av.y + bv.y, 0.f));
                    hv.z = f2tf32(fmaxf(av.z + bv.z, 0.f));
                    hv.w = f2tf32(fmaxf(av.w + bv.w, 0.f));
                    *(uint4*)(hr + j * 4) = hv;
                }
            } else {
#pragma unroll
                for (int j = 0; j < 16; j++)
                    *(uint4*)(hr + j * 4) = make_uint4(0u, 0u, 0u, 0u);
            }
        }
        __syncthreads();

        // ---- MMA: warp tile 32 edges x 64 outs ----
        float acc[2][8][4];
#pragma unroll
        for (int mt = 0; mt < 2; mt++)
#pragma unroll
            for (int nt = 0; nt < 8; nt++)
#pragma unroll
                for (int r = 0; r < 4; r++) acc[mt][nt][r] = 0.f;

        const int g = lane >> 2, th = lane & 3;
#pragma unroll 4
        for (int kk = 0; kk < 16; kk++) {
            uint32_t a[2][4];
#pragma unroll
            for (int mt = 0; mt < 2; mt++) {
                const uint32_t* base = Hs + (wM * 32 + mt * 16 + g) * HP + kk * 8 + th;
                a[mt][0] = base[0];
                a[mt][1] = base[8 * HP];
                a[mt][2] = base[4];
                a[mt][3] = base[8 * HP + 4];
            }
#pragma unroll
            for (int p = 0; p < 4; p++) {
                uint4 bp = wbs[((wN * 4 + p) * 16 + kk) * 32 + lane];
#pragma unroll
                for (int mt = 0; mt < 2; mt++) {
                    mma_tf32(acc[mt][2 * p],     a[mt], bp.x, bp.y);
                    mma_tf32(acc[mt][2 * p + 1], a[mt], bp.z, bp.w);
                }
            }
        }
        __syncthreads();   // all warps done reading H

        // ---- store D -> msg[e][c] ----
#pragma unroll
        for (int mt = 0; mt < 2; mt++) {
            const int row = wM * 32 + mt * 16 + g;
#pragma unroll
            for (int nt = 0; nt < 8; nt++) {
                const int col = wN * 64 + nt * 8 + 2 * th;
                *(float2*)(msg + row * HP + col) =
                    make_float2(acc[mt][nt][0], acc[mt][nt][1]);
                *(float2*)(msg + (row + 8) * HP + col) =
                    make_float2(acc[mt][nt][2], acc[mt][nt][3]);
            }
        }
        __syncthreads();

        // ---- segmented max + writeback ----
        {
            const int nseg = snseg[0];
            for (int i = tid; i < nseg * 128; i += 256) {
                const int c = i & 127;
                const int s = i >> 7;
                const int st = segs[s], en = segs[s + 1];
                float m = -3.4e38f;
                for (int e = st; e < en; e++)
                    m = fmaxf(m, msg[e * HP + c]);
                m += bbs[c];
                float* o = out + (size_t)segn[s] * OC + c;
                if (st == 0 || en == cnt) {
                    atomicMax((int*)o, __float_as_int(m));  // 0-init => relu free
                } else {
                    *o = fmaxf(m, 0.f);                     // sole writer
                }
            }
        }
        __syncthreads();
    }
}

// ---------------------------------------------------------------------------
// Final: concat(x2,x4,x6) [384] -> maxpool(24) -> 16 -> @ fw + fb
// ---------------------------------------------------------------------------
__global__ __launch_bounds__(256)
void final_kernel(const float* __restrict__ x2,
                  const float* __restrict__ x4,
                  const float* __restrict__ x6,
                  const float* __restrict__ fw,
                  const float* __restrict__ fb,
                  float* __restrict__ out,
                  int n_nodes)
{
    const unsigned FULL = 0xffffffffu;
    const int lane = threadIdx.x & 31;
    const int warp = blockIdx.x * (blockDim.x >> 5) + (threadIdx.x >> 5);
    const int nw   = gridDim.x * (blockDim.x >> 5);

    for (int n = warp; n < n_nodes; n += nw) {
        float m = -3.4e38f;
        int idx0 = lane * 12;
#pragma unroll
        for (int i = 0; i < 12; i++) {
            int idx = idx0 + i;
            float v;
            if (idx < 128)       v = x2[(size_t)n * OC + idx];
            else if (idx < 256)  v = x4[(size_t)n * OC + idx - 128];
            else                 v = x6[(size_t)n * OC + idx - 256];
            m = fmaxf(m, v);
        }
        float mm = fmaxf(m, __shfl_xor_sync(FULL, m, 1));
        float part = ((lane & 1) == 0) ? mm * fw[lane >> 1] : 0.f;
#pragma unroll
        for (int off = 16; off >= 1; off >>= 1)
            part += __shfl_xor_sync(FULL, part, off);
        if (lane == 0) out[n] = part + fb[0];
    }
}

// ---------------------------------------------------------------------------
extern "C" void kernel_launch(void* const* d_in, const int* in_sizes, int n_in,
                              void* d_out, int out_size)
{
    const float* x   = (const float*)d_in[0];
    const void*  ei  = d_in[1];
    const float* w1a = (const float*)d_in[2];  const float* b1a = (const float*)d_in[3];
    const float* w1b = (const float*)d_in[4];  const float* b1b = (const float*)d_in[5];
    const float* w2a = (const float*)d_in[6];  const float* b2a = (const float*)d_in[7];
    const float* w2b = (const float*)d_in[8];  const float* b2b = (const float*)d_in[9];
    const float* w3a = (const float*)d_in[10]; const float* b3a = (const float*)d_in[11];
    const float* w3b = (const float*)d_in[12]; const float* b3b = (const float*)d_in[13];
    const float* fw  = (const float*)d_in[14]; const float* fb  = (const float*)d_in[15];
    float* out = (float*)d_out;

    const int       N = in_sizes[0] / 24;
    const long long E = in_sizes[1] / 2;

    float *A, *B, *X2, *X4, *X6;
    int *deg, *off, *cur, *ssrc, *sdst;
    uint4 *wbp;
    cudaGetSymbolAddress((void**)&A,    g_A);
    cudaGetSymbolAddress((void**)&B,    g_B);
    cudaGetSymbolAddress((void**)&X2,   g_x2);
    cudaGetSymbolAddress((void**)&X4,   g_x4);
    cudaGetSymbolAddress((void**)&X6,   g_x6);
    cudaGetSymbolAddress((void**)&deg,  g_deg);
    cudaGetSymbolAddress((void**)&off,  g_off);
    cudaGetSymbolAddress((void**)&cur,  g_cur);
    cudaGetSymbolAddress((void**)&ssrc, g_ssrc);
    cudaGetSymbolAddress((void**)&sdst, g_sdst);
    cudaGetSymbolAddress((void**)&wbp,  g_wbp);

    cudaFuncSetAttribute(edge_mma_kernel,
                         cudaFuncAttributeMaxDynamicSharedMemorySize, SM_TOTAL);

    // ---- edge-index width + counting sort by dst ----
    detect_idx_kernel<<<1, 256>>>((const int*)ei);
    cudaMemsetAsync(deg, 0, (size_t)N * sizeof(int));
    cudaMemsetAsync(cur, 0, (size_t)N * sizeof(int));
    hist_kernel<<<512, 256>>>(ei, E, deg);
    scan_kernel<<<1, 1024>>>(deg, off, N);
    scatter_kernel<<<512, 256>>>(ei, E, off, cur, ssrc, sdst);

    // ---- weight prep (tf32 packed B fragments) ----
    prep_w_kernel<<<16, 256>>>(w1b, wbp);
    prep_w_kernel<<<16, 256>>>(w2b, wbp + 4096);
    prep_w_kernel<<<16, 256>>>(w3b, wbp + 8192);

    const int NPB = 8;
    const int node_grid = (N + NPB - 1) / NPB;
    const int edge_grid = 148;

    // Layer 1 (C = 24)
    node_kernel<24, 8><<<node_grid, 128>>>(x, w1a, b1a, A, B, X2, N);
    edge_mma_kernel<<<edge_grid, 256, SM_TOTAL>>>((const float4*)A, (const float4*)B,
        ssrc, sdst, wbp, b1b, X2, (int)E);
    // Layer 2 (C = 128)
    node_kernel<128, 8><<<node_grid, 128>>>(X2, w2a, b2a, A, B, X4, N);
    edge_mma_kernel<<<edge_grid, 256, SM_TOTAL>>>((const float4*)A, (const float4*)B,
        ssrc, sdst, wbp + 4096, b2b, X4, (int)E);
    // Layer 3 (C = 128)
    node_kernel<128, 8><<<node_grid, 128>>>(X4, w3a, b3a, A, B, X6, N);
    edge_mma_kernel<<<edge_grid, 256, SM_TOTAL>>>((const float4*)A, (const float4*)B,
        ssrc, sdst, wbp + 8192, b3b, X6, (int)E);

    // Pool + final linear
    final_kernel<<<(N + 7) / 8, 256>>>(X2, X4, X6, fw, fb, out, N);
}